// round 12
// baseline (speedup 1.0000x reference)
#include <cuda_runtime.h>
#include <cuda_bf16.h>

// x shape (64, 20, 64, 32, 32) fp32 ; B=64, CHI=20, D=65536
#define B_        64
#define CHI_      20
#define D_        65536
#define NB_       32                 // CTAs cooperating on one batch
#define NGRP_     4                  // independent groups (concurrent batches)
#define GRID_     (NB_ * NGRP_)      // 128 CTAs, 1/SM (<=148 -> all co-resident)
#define THREADS_  256
#define CHUNK_    (D_ / NB_)         // 2048 d-indices per CTA
#define DPT_      (CHUNK_ / THREADS_)// 8 d per thread
#define ITERS_    (B_ / NGRP_)       // 16 batches per group
#define SMEM_BYTES_ (5 * CHUNK_ * sizeof(float4))   // 163840 B

// Cross-CTA scratch (no cudaMalloc). 128B-padded rows: L1 not coherent
// across SMs, keep writers on distinct lines.
__device__ float g_part[B_][NB_][32];   // per-(batch,cta): [0]=accA,[1]=accB
__device__ float g_alpha[B_][32];       // softmax weights per batch
__device__ int   g_cnt1[B_];            // phase-1 arrivals
__device__ int   g_flag[B_];            // alpha-ready flag
__device__ int   g_cnt2[B_];            // phase-2 arrivals (reset bookkeeping)

extern __shared__ float4 s_cache[];     // [5][CHUNK_] staged transposed-view data

__global__ __launch_bounds__(THREADS_, 1)
void fused_attn_kernel(const float* __restrict__ x, float* __restrict__ out) {
    const int cta  = blockIdx.x;
    const int grp  = cta / NB_;
    const int k    = cta % NB_;
    const int tid  = threadIdx.x;
    const int lane = tid & 31;
    const int wid  = tid >> 5;

    __shared__ float s_red[THREADS_ / 32][2];
    __shared__ float s_alpha[CHI_];
    __shared__ int   s_arrival;

    // This CTA's chunk covers flat offsets [s0, s0+40960) of each batch.
    // 40960 < 65536 => at most two frames rows: c_lo and possibly c_lo+1.
    const int s0    = k * CHUNK_ * CHI_;      // flat start (elements)
    const int c_lo  = s0 >> 16;               // first frames row touched

    for (int it = 0; it < ITERS_; ++it) {
        const int    b    = grp * ITERS_ + it;
        const size_t base = (size_t)b * CHI_ * D_;
        const int    d0   = k * CHUNK_;
        const float* __restrict__ lastp = x + base + (size_t)(CHI_ - 1) * D_;

        // ===== Phase 1: single DRAM stream; bin dot-contributions by
        // frames row c = f>>16, multiplier last[f & 0xFFFF].
        float accA = 0.0f, accB = 0.0f;

        #pragma unroll
        for (int i = 0; i < DPT_; i++) {
            const int dl    = tid + i * THREADS_;       // local d in [0,CHUNK_)
            const int fbase = (d0 + dl) * CHI_;         // flat offset of group
            const float4* __restrict__ p =
                reinterpret_cast<const float4*>(x + base + (size_t)fbase);
            #pragma unroll
            for (int j = 0; j < 5; j++) {
                const int f  = fbase + 4 * j;           // flat offset (mult of 4)
                const int dd = f & 0xFFFF;              // d within frames row
                float4 v = __ldcs(p + j);               // streaming main load
                float4 l = *reinterpret_cast<const float4*>(lastp + dd);
                s_cache[j * CHUNK_ + dl] = v;
                float dot = v.x * l.x;
                dot = fmaf(v.y, l.y, dot);
                dot = fmaf(v.z, l.z, dot);
                dot = fmaf(v.w, l.w, dot);
                if ((f >> 16) == c_lo) accA += dot;     // predicated adds
                else                   accB += dot;
            }
        }

        // Block-reduce the two accumulators (fixed order -> deterministic)
        #pragma unroll
        for (int off = 16; off > 0; off >>= 1) {
            accA += __shfl_down_sync(0xFFFFFFFFu, accA, off);
            accB += __shfl_down_sync(0xFFFFFFFFu, accB, off);
        }
        if (lane == 0) { s_red[wid][0] = accA; s_red[wid][1] = accB; }
        __syncthreads();
        if (tid < 2) {
            float v = 0.0f;
            #pragma unroll
            for (int w = 0; w < THREADS_ / 32; w++) v += s_red[w][tid];
            g_part[b][k][tid] = v;
        }
        __threadfence();                                 // release partials
        __syncthreads();

        if (tid == 0)
            s_arrival = atomicAdd(&g_cnt1[b], 1);
        __syncthreads();

        // Last-arriving CTA: assemble scores, softmax, publish alpha
        if (s_arrival == NB_ - 1 && wid == 0) {
            __threadfence();                             // acquire partials
            float s = 0.0f;
            #pragma unroll
            for (int kk = 0; kk < NB_; kk++) {
                const int st  = kk * CHUNK_ * CHI_;
                const int clo = st >> 16;
                const int chi = (st + CHUNK_ * CHI_ - 1) >> 16;
                float p0 = __ldcg(&g_part[b][kk][0]);
                float p1 = __ldcg(&g_part[b][kk][1]);
                if (lane == clo) s += p0;
                if (lane == chi) s += p1;                // p1==0 if no straddle
            }
            s *= (1.0f / (float)CHI_);
            float sv = (lane < CHI_) ? s : -1e30f;
            #pragma unroll
            for (int off = 16; off > 0; off >>= 1)
                sv = fmaxf(sv, __shfl_xor_sync(0xFFFFFFFFu, sv, off));
            float e = (lane < CHI_) ? __expf(s - sv) : 0.0f;
            float z = e;
            #pragma unroll
            for (int off = 16; off > 0; off >>= 1)
                z += __shfl_xor_sync(0xFFFFFFFFu, z, off);
            if (lane < CHI_)
                g_alpha[b][lane] = e / z;
            __threadfence();                             // release alpha
            if (lane == 0)
                atomicExch(&g_flag[b], 1);
        }

        // ===== Wait for alpha
        if (tid == 0) {
            while (((volatile int*)g_flag)[b] == 0) __nanosleep(64);
            __threadfence();                             // acquire alpha
        }
        __syncthreads();
        if (tid < CHI_)
            s_alpha[tid] = __ldcg(&g_alpha[b][tid]);
        __syncthreads();

        // ===== Phase 2: output from SMEM — zero extra DRAM read.
        // out[b,d] = sum_c flat[d*20+c] * alpha[c]  (transposed-view einsum)
        float al[CHI_];
        #pragma unroll
        for (int c = 0; c < CHI_; c++) al[c] = s_alpha[c];

        #pragma unroll
        for (int i = 0; i < DPT_; i++) {
            const int dl = tid + i * THREADS_;
            float r = 0.0f;
            #pragma unroll
            for (int j = 0; j < 5; j++) {
                float4 v = s_cache[j * CHUNK_ + dl];
                r = fmaf(v.x, al[j * 4 + 0], r);
                r = fmaf(v.y, al[j * 4 + 1], r);
                r = fmaf(v.z, al[j * 4 + 2], r);
                r = fmaf(v.w, al[j * 4 + 3], r);
            }
            out[(size_t)b * D_ + d0 + dl] = r;
        }

        // ===== Self-clean for the next graph replay
        __syncthreads();
        if (tid == 0) {
            int o = atomicAdd(&g_cnt2[b], 1);
            if (o == NB_ - 1) {
                g_cnt1[b] = 0;
                g_flag[b] = 0;
                __threadfence();
                g_cnt2[b] = 0;
            }
        }
        // s_cache slots are thread-private (same thread writes & reads them),
        // so no extra sync needed before the next iteration overwrites them.
    }
}

extern "C" void kernel_launch(void* const* d_in, const int* in_sizes, int n_in,
                              void* d_out, int out_size) {
    const float* x   = (const float*)d_in[0];
    float*       out = (float*)d_out;

    static bool attr_done = false;
    if (!attr_done) {
        cudaFuncSetAttribute(fused_attn_kernel,
                             cudaFuncAttributeMaxDynamicSharedMemorySize,
                             (int)SMEM_BYTES_);
        attr_done = true;
    }

    fused_attn_kernel<<<GRID_, THREADS_, SMEM_BYTES_>>>(x, out);
}